// round 1
// baseline (speedup 1.0000x reference)
#include <cuda_runtime.h>
#include <cuda_bf16.h>
#include <cstdint>
#include <cstddef>

// ---------------------------------------------------------------------------
// ScaleCausalAttention  (B=64, N=341, D=768, H=12, hd=64, fp32)
//   qkv  = x @ qkv_w^T + qkv_b
//   attn = softmax(q k^T * 0.125 + scale-causal mask) v      (per b,h)
//   out  = attn @ proj_w^T + proj_b
//
// GEMMs: tf32 mma.sync (m16n8k8), 128x128x32 tiles, fp32 accum.
// Attention: fp32 SIMT, K/V in smem, mask == per-query loop bound.
// ---------------------------------------------------------------------------

#define NTOK   341
#define DMODEL 768
#define NHEAD  12
#define HDIM   64

// Scratch (allocation-free rule: __device__ globals)
__device__ float g_qkv [64ULL * NTOK * 3 * DMODEL];   // [B*N, 2304]
__device__ float g_attn[64ULL * NTOK * DMODEL];       // [B*N, 768]

// ---------------------------------------------------------------------------
// tf32 helpers
// ---------------------------------------------------------------------------
__device__ __forceinline__ float to_tf32f(float x) {
    uint32_t u;
    asm("cvt.rna.tf32.f32 %0, %1;" : "=r"(u) : "f"(x));
    return __uint_as_float(u);
}

__device__ __forceinline__ void mma_tf32(float c[4],
                                         uint32_t a0, uint32_t a1, uint32_t a2, uint32_t a3,
                                         uint32_t b0, uint32_t b1) {
    asm volatile(
        "mma.sync.aligned.m16n8k8.row.col.f32.tf32.tf32.f32 "
        "{%0,%1,%2,%3}, {%4,%5,%6,%7}, {%8,%9}, {%0,%1,%2,%3};\n"
        : "+f"(c[0]), "+f"(c[1]), "+f"(c[2]), "+f"(c[3])
        : "r"(a0), "r"(a1), "r"(a2), "r"(a3), "r"(b0), "r"(b1));
}

// ---------------------------------------------------------------------------
// GEMM: C[M,N] = A[M,K] @ W[N,K]^T + bias[N]
// Block tile 128x128, K-tile 32, 256 threads (8 warps in 2x4, warp tile 64x32).
// N and K are multiples of 128/32 for all call sites; only M is ragged.
// ---------------------------------------------------------------------------
__global__ __launch_bounds__(256, 2)
void gemm_tf32_bias(const float* __restrict__ A, const float* __restrict__ W,
                    const float* __restrict__ bias, float* __restrict__ C,
                    int M, int N, int K)
{
    __shared__ float As[128][36];   // pad 36 -> conflict-free fragment LDS
    __shared__ float Bs[128][36];

    const int tid  = threadIdx.x;
    const int bm   = blockIdx.y * 128;
    const int bn   = blockIdx.x * 128;
    const int warp = tid >> 5;
    const int lane = tid & 31;
    const int wm   = (warp >> 2) * 64;   // 0 / 64
    const int wn   = (warp & 3) * 32;    // 0 / 32 / 64 / 96
    const int g    = lane >> 2;          // groupID 0..7
    const int ctg  = lane & 3;           // thread-in-group 0..3

    float acc[4][4][4];
    #pragma unroll
    for (int mt = 0; mt < 4; mt++)
        #pragma unroll
        for (int nt = 0; nt < 4; nt++)
            #pragma unroll
            for (int i = 0; i < 4; i++) acc[mt][nt][i] = 0.0f;

    const int lr = tid >> 3;         // 0..31 (rows lr, lr+32, lr+64, lr+96)
    const int lc = (tid & 7) * 4;    // float4 column

    for (int k0 = 0; k0 < K; k0 += 32) {
        #pragma unroll
        for (int i = 0; i < 4; i++) {
            const int row = lr + i * 32;
            // A tile (guard ragged M, zero-fill)
            float4 av = make_float4(0.f, 0.f, 0.f, 0.f);
            const int gm = bm + row;
            if (gm < M) av = *(const float4*)(A + (size_t)gm * K + k0 + lc);
            float4 ac = make_float4(to_tf32f(av.x), to_tf32f(av.y),
                                    to_tf32f(av.z), to_tf32f(av.w));
            *(float4*)&As[row][lc] = ac;
            // W tile (N always divisible by 128 here)
            float4 wv = *(const float4*)(W + (size_t)(bn + row) * K + k0 + lc);
            float4 wc = make_float4(to_tf32f(wv.x), to_tf32f(wv.y),
                                    to_tf32f(wv.z), to_tf32f(wv.w));
            *(float4*)&Bs[row][lc] = wc;
        }
        __syncthreads();

        #pragma unroll
        for (int kk = 0; kk < 32; kk += 8) {
            uint32_t af[4][4], bf[4][2];
            #pragma unroll
            for (int mt = 0; mt < 4; mt++) {
                const int r = wm + mt * 16 + g;
                af[mt][0] = __float_as_uint(As[r    ][kk + ctg    ]);
                af[mt][1] = __float_as_uint(As[r + 8][kk + ctg    ]);
                af[mt][2] = __float_as_uint(As[r    ][kk + ctg + 4]);
                af[mt][3] = __float_as_uint(As[r + 8][kk + ctg + 4]);
            }
            #pragma unroll
            for (int nt = 0; nt < 4; nt++) {
                const int c = wn + nt * 8 + g;
                bf[nt][0] = __float_as_uint(Bs[c][kk + ctg    ]);
                bf[nt][1] = __float_as_uint(Bs[c][kk + ctg + 4]);
            }
            #pragma unroll
            for (int mt = 0; mt < 4; mt++)
                #pragma unroll
                for (int nt = 0; nt < 4; nt++)
                    mma_tf32(acc[mt][nt],
                             af[mt][0], af[mt][1], af[mt][2], af[mt][3],
                             bf[nt][0], bf[nt][1]);
        }
        __syncthreads();
    }

    // Epilogue: C layout c0=(g,2ctg) c1=(g,2ctg+1) c2=(g+8,2ctg) c3=(g+8,2ctg+1)
    #pragma unroll
    for (int mt = 0; mt < 4; mt++) {
        #pragma unroll
        for (int nt = 0; nt < 4; nt++) {
            const int r0 = bm + wm + mt * 16 + g;
            const int c0 = bn + wn + nt * 8 + 2 * ctg;
            const float b0 = bias[c0];
            const float b1 = bias[c0 + 1];
            if (r0 < M) {
                float2 v = make_float2(acc[mt][nt][0] + b0, acc[mt][nt][1] + b1);
                *(float2*)(C + (size_t)r0 * N + c0) = v;
            }
            if (r0 + 8 < M) {
                float2 v = make_float2(acc[mt][nt][2] + b0, acc[mt][nt][3] + b1);
                *(float2*)(C + (size_t)(r0 + 8) * N + c0) = v;
            }
        }
    }
}

// ---------------------------------------------------------------------------
// Attention: one CTA per (b,h). K/V tiles (341x64 fp32 each) in dynamic smem.
// One thread per query row; single-pass softmax (no max-sub: logits are small
// by construction, exp() is stable and the math is identical to the reference).
// Scale-causal mask == loop bound: query in scale s attends j < cum[s+1]
// (CLS row s=0 attends all 341).
// ---------------------------------------------------------------------------
#define ATTN_THREADS 352
#define ATTN_SMEM    (2 * NTOK * HDIM * (int)sizeof(float))   // 174592 B

__global__ __launch_bounds__(ATTN_THREADS, 1)
void attn_kernel(const float* __restrict__ qkv, float* __restrict__ attn_out, int Bsz)
{
    extern __shared__ float sm[];
    float* Ks = sm;
    float* Vs = sm + NTOK * HDIM;

    const int h = blockIdx.x;   // 0..11
    const int b = blockIdx.y;   // 0..B-1
    const int tid = threadIdx.x;
    const float* base = qkv + (size_t)b * NTOK * (3 * DMODEL) + h * HDIM;

    // cooperative K/V load (rows of 64 floats, float4 granular)
    for (int i = tid; i < NTOK * (HDIM / 4); i += ATTN_THREADS) {
        const int row = i >> 4;
        const int c4  = (i & 15) << 2;
        const float* rp = base + (size_t)row * (3 * DMODEL);
        *(float4*)(Ks + row * HDIM + c4) = *(const float4*)(rp + DMODEL   + c4);
        *(float4*)(Vs + row * HDIM + c4) = *(const float4*)(rp + 2*DMODEL + c4);
    }
    __syncthreads();

    const int t = tid;
    if (t < NTOK) {
        // load q row into registers
        float q[HDIM];
        const float* qp = base + (size_t)t * (3 * DMODEL);
        #pragma unroll
        for (int i = 0; i < HDIM / 4; i++) {
            float4 v = *(const float4*)(qp + i * 4);
            q[i*4+0] = v.x; q[i*4+1] = v.y; q[i*4+2] = v.z; q[i*4+3] = v.w;
        }

        // mask -> loop bound (cum = 0,1,5,21,85,341; CLS sees everything)
        const int jmax = (t == 0) ? NTOK
                       : (t < 5)  ? 5
                       : (t < 21) ? 21
                       : (t < 85) ? 85
                       : NTOK;

        float o[HDIM];
        #pragma unroll
        for (int d = 0; d < HDIM; d++) o[d] = 0.0f;
        float l = 0.0f;

        for (int j = 0; j < jmax; j++) {
            const float4* kr = (const float4*)(Ks + j * HDIM);
            float s0 = 0.f, s1 = 0.f, s2 = 0.f, s3 = 0.f;
            #pragma unroll
            for (int i = 0; i < HDIM / 4; i++) {
                float4 kv = kr[i];
                s0 += q[i*4+0] * kv.x; s1 += q[i*4+1] * kv.y;
                s2 += q[i*4+2] * kv.z; s3 += q[i*4+3] * kv.w;
            }
            const float e = __expf(((s0 + s1) + (s2 + s3)) * 0.125f);
            l += e;
            const float4* vr = (const float4*)(Vs + j * HDIM);
            #pragma unroll
            for (int i = 0; i < HDIM / 4; i++) {
                float4 vv = vr[i];
                o[i*4+0] += e * vv.x; o[i*4+1] += e * vv.y;
                o[i*4+2] += e * vv.z; o[i*4+3] += e * vv.w;
            }
        }

        const float inv = 1.0f / l;
        float* op = attn_out + ((size_t)b * NTOK + t) * DMODEL + h * HDIM;
        #pragma unroll
        for (int i = 0; i < HDIM / 4; i++) {
            float4 v = make_float4(o[i*4+0]*inv, o[i*4+1]*inv, o[i*4+2]*inv, o[i*4+3]*inv);
            *(float4*)(op + i * 4) = v;
        }
    }
}

// ---------------------------------------------------------------------------
// Launch
// ---------------------------------------------------------------------------
extern "C" void kernel_launch(void* const* d_in, const int* in_sizes, int n_in,
                              void* d_out, int out_size)
{
    const float* x      = (const float*)d_in[0];
    const float* qkv_w  = (const float*)d_in[1];
    const float* qkv_b  = (const float*)d_in[2];
    const float* proj_w = (const float*)d_in[3];
    const float* proj_b = (const float*)d_in[4];
    float* out = (float*)d_out;

    const int Bsz = in_sizes[0] / (NTOK * DMODEL);   // 64
    const int M   = Bsz * NTOK;                      // 21824

    float *qkv_s, *attn_s;
    cudaGetSymbolAddress((void**)&qkv_s,  g_qkv);
    cudaGetSymbolAddress((void**)&attn_s, g_attn);

    cudaFuncSetAttribute(attn_kernel,
                         cudaFuncAttributeMaxDynamicSharedMemorySize, ATTN_SMEM);

    // 1) QKV GEMM: [M,768] x [2304,768]^T -> [M,2304]
    {
        dim3 grid(3 * DMODEL / 128, (M + 127) / 128);
        gemm_tf32_bias<<<grid, 256>>>(x, qkv_w, qkv_b, qkv_s, M, 3 * DMODEL, DMODEL);
    }
    // 2) Attention
    {
        dim3 grid(NHEAD, Bsz);
        attn_kernel<<<grid, ATTN_THREADS, ATTN_SMEM>>>(qkv_s, attn_s, Bsz);
    }
    // 3) Proj GEMM: [M,768] x [768,768]^T -> [M,768]
    {
        dim3 grid(DMODEL / 128, (M + 127) / 128);
        gemm_tf32_bias<<<grid, 256>>>(attn_s, proj_w, proj_b, out, M, DMODEL, DMODEL);
    }
}

// round 3
// speedup vs baseline: 1.4469x; 1.4469x over previous
#include <cuda_runtime.h>
#include <cuda_bf16.h>
#include <cstdint>
#include <cstddef>

// ---------------------------------------------------------------------------
// ScaleCausalAttention  (B=64, N=341, D=768, H=12, hd=64, fp32)
//   qkv  = x @ qkv_w^T + qkv_b
//   attn = softmax(q k^T * 0.125 + scale-causal mask) v      (per b,h)
//   out  = attn @ proj_w^T + proj_b
//
// GEMMs: tf32 mma.sync (m16n8k8), 128x128x32 tiles, fp32 accum.
// Attention: tf32 tensor-core flash attention, 1 CTA per (b,h).
// ---------------------------------------------------------------------------

#define NTOK   341
#define DMODEL 768
#define NHEAD  12
#define HDIM   64

// Scratch (allocation-free rule: __device__ globals)
__device__ float g_qkv [64ULL * NTOK * 3 * DMODEL];   // [B*N, 2304]
__device__ float g_attn[64ULL * NTOK * DMODEL];       // [B*N, 768]

// ---------------------------------------------------------------------------
// tf32 helpers
// ---------------------------------------------------------------------------
__device__ __forceinline__ float to_tf32f(float x) {
    uint32_t u;
    asm("cvt.rna.tf32.f32 %0, %1;" : "=r"(u) : "f"(x));
    return __uint_as_float(u);
}

__device__ __forceinline__ void mma_tf32(float c[4],
                                         uint32_t a0, uint32_t a1, uint32_t a2, uint32_t a3,
                                         uint32_t b0, uint32_t b1) {
    asm volatile(
        "mma.sync.aligned.m16n8k8.row.col.f32.tf32.tf32.f32 "
        "{%0,%1,%2,%3}, {%4,%5,%6,%7}, {%8,%9}, {%0,%1,%2,%3};\n"
        : "+f"(c[0]), "+f"(c[1]), "+f"(c[2]), "+f"(c[3])
        : "r"(a0), "r"(a1), "r"(a2), "r"(a3), "r"(b0), "r"(b1));
}

// ---------------------------------------------------------------------------
// GEMM: C[M,N] = A[M,K] @ W[N,K]^T + bias[N]
// Block tile 128x128, K-tile 32, 256 threads (8 warps in 2x4, warp tile 64x32).
// ---------------------------------------------------------------------------
__global__ __launch_bounds__(256, 2)
void gemm_tf32_bias(const float* __restrict__ A, const float* __restrict__ W,
                    const float* __restrict__ bias, float* __restrict__ C,
                    int M, int N, int K)
{
    __shared__ float As[128][36];
    __shared__ float Bs[128][36];

    const int tid  = threadIdx.x;
    const int bm   = blockIdx.y * 128;
    const int bn   = blockIdx.x * 128;
    const int warp = tid >> 5;
    const int lane = tid & 31;
    const int wm   = (warp >> 2) * 64;
    const int wn   = (warp & 3) * 32;
    const int g    = lane >> 2;
    const int ctg  = lane & 3;

    float acc[4][4][4];
    #pragma unroll
    for (int mt = 0; mt < 4; mt++)
        #pragma unroll
        for (int nt = 0; nt < 4; nt++)
            #pragma unroll
            for (int i = 0; i < 4; i++) acc[mt][nt][i] = 0.0f;

    const int lr = tid >> 3;
    const int lc = (tid & 7) * 4;

    for (int k0 = 0; k0 < K; k0 += 32) {
        #pragma unroll
        for (int i = 0; i < 4; i++) {
            const int row = lr + i * 32;
            float4 av = make_float4(0.f, 0.f, 0.f, 0.f);
            const int gm = bm + row;
            if (gm < M) av = *(const float4*)(A + (size_t)gm * K + k0 + lc);
            float4 ac = make_float4(to_tf32f(av.x), to_tf32f(av.y),
                                    to_tf32f(av.z), to_tf32f(av.w));
            *(float4*)&As[row][lc] = ac;
            float4 wv = *(const float4*)(W + (size_t)(bn + row) * K + k0 + lc);
            float4 wc = make_float4(to_tf32f(wv.x), to_tf32f(wv.y),
                                    to_tf32f(wv.z), to_tf32f(wv.w));
            *(float4*)&Bs[row][lc] = wc;
        }
        __syncthreads();

        #pragma unroll
        for (int kk = 0; kk < 32; kk += 8) {
            uint32_t af[4][4], bf[4][2];
            #pragma unroll
            for (int mt = 0; mt < 4; mt++) {
                const int r = wm + mt * 16 + g;
                af[mt][0] = __float_as_uint(As[r    ][kk + ctg    ]);
                af[mt][1] = __float_as_uint(As[r + 8][kk + ctg    ]);
                af[mt][2] = __float_as_uint(As[r    ][kk + ctg + 4]);
                af[mt][3] = __float_as_uint(As[r + 8][kk + ctg + 4]);
            }
            #pragma unroll
            for (int nt = 0; nt < 4; nt++) {
                const int c = wn + nt * 8 + g;
                bf[nt][0] = __float_as_uint(Bs[c][kk + ctg    ]);
                bf[nt][1] = __float_as_uint(Bs[c][kk + ctg + 4]);
            }
            #pragma unroll
            for (int mt = 0; mt < 4; mt++)
                #pragma unroll
                for (int nt = 0; nt < 4; nt++)
                    mma_tf32(acc[mt][nt],
                             af[mt][0], af[mt][1], af[mt][2], af[mt][3],
                             bf[nt][0], bf[nt][1]);
        }
        __syncthreads();
    }

    #pragma unroll
    for (int mt = 0; mt < 4; mt++) {
        #pragma unroll
        for (int nt = 0; nt < 4; nt++) {
            const int r0 = bm + wm + mt * 16 + g;
            const int c0 = bn + wn + nt * 8 + 2 * ctg;
            const float b0 = bias[c0];
            const float b1 = bias[c0 + 1];
            if (r0 < M) {
                float2 v = make_float2(acc[mt][nt][0] + b0, acc[mt][nt][1] + b1);
                *(float2*)(C + (size_t)r0 * N + c0) = v;
            }
            if (r0 + 8 < M) {
                float2 v = make_float2(acc[mt][nt][2] + b0, acc[mt][nt][3] + b1);
                *(float2*)(C + (size_t)(r0 + 8) * N + c0) = v;
            }
        }
    }
}

// ---------------------------------------------------------------------------
// Flash attention (tf32 tensor cores), one CTA per (b,h).
//   11 warps x 32 query rows = 352 (>=341).  6 key tiles of 64 (=384>=341).
//   Single-pass softmax (no max-sub; logits are small by construction).
//   smem strides: 68 = 4 (mod 32), 72 = 8 (mod 32) -> all fragment LDS
//   conflict-free (banks 4g+ctg resp. 8ctg+g).
// ---------------------------------------------------------------------------
#define FA_THREADS 352
#define QS_STRIDE  68
#define KS_STRIDE  68
#define VS_STRIDE  72
#define PS_STRIDE  68
#define QS_FLOATS  (352 * QS_STRIDE)          // 23936
#define KS_FLOATS  (64 * KS_STRIDE)           // 4352
#define VS_FLOATS  (64 * VS_STRIDE)           // 4608
#define PS_FLOATS  (11 * 32 * PS_STRIDE)      // 23936
#define FA_SMEM_FLOATS (QS_FLOATS + KS_FLOATS + VS_FLOATS + PS_FLOATS)
#define FA_SMEM_BYTES  (FA_SMEM_FLOATS * 4)   // 227328 B  (< 232448 opt-in limit)

__device__ __forceinline__ int jmax_of(int t) {
    if (t >= 341) return 5;      // padded rows: harmless, discarded
    if (t == 0 || t >= 85) return 341;
    if (t < 5)  return 5;
    if (t < 21) return 21;
    return 85;
}

__global__ __launch_bounds__(FA_THREADS, 1)
void flash_attn_tf32(const float* __restrict__ qkv, float* __restrict__ attn_out)
{
    extern __shared__ float sm[];
    float* Qs = sm;                          // [352][68]
    float* Ks = Qs + QS_FLOATS;              // [64][68]
    float* Vs = Ks + KS_FLOATS;              // [64][72]
    float* Pb = Vs + VS_FLOATS;              // [11][32][68]

    const int h   = blockIdx.x;
    const int b   = blockIdx.y;
    const int tid = threadIdx.x;
    const int w   = tid >> 5;
    const int lane = tid & 31;
    const int g    = lane >> 2;
    const int ctg  = lane & 3;
    float* Pw = Pb + w * 32 * PS_STRIDE;

    const float* base = qkv + (size_t)b * NTOK * (3 * DMODEL) + h * HDIM;

    // ---- stage Q (tf32-rounded), rows >= 341 zero-filled
    for (int idx = tid; idx < 352 * 16; idx += FA_THREADS) {
        const int row = idx >> 4;
        const int d4  = (idx & 15) << 2;
        float4 v = make_float4(0.f, 0.f, 0.f, 0.f);
        if (row < NTOK) v = *(const float4*)(base + (size_t)row * (3 * DMODEL) + d4);
        *(float4*)&Qs[row * QS_STRIDE + d4] =
            make_float4(to_tf32f(v.x), to_tf32f(v.y), to_tf32f(v.z), to_tf32f(v.w));
    }

    // O accumulators (32x64 per warp) and row-sum partials
    float o[2][8][4];
    #pragma unroll
    for (int mt = 0; mt < 2; mt++)
        #pragma unroll
        for (int nt = 0; nt < 8; nt++)
            #pragma unroll
            for (int i = 0; i < 4; i++) o[mt][nt][i] = 0.f;
    float lsum[2][2] = {{0.f, 0.f}, {0.f, 0.f}};

    const int wmax = (w == 1) ? 85 : 341;   // rows 32..63 attend only 85 keys
    const int jm0a = jmax_of(w * 32      + g);
    const int jm0b = jmax_of(w * 32 +  8 + g);
    const int jm1a = jmax_of(w * 32 + 16 + g);
    const int jm1b = jmax_of(w * 32 + 24 + g);

    for (int kt = 0; kt < 6; kt++) {
        __syncthreads();   // everyone done with previous K/V tile (and Q staged on kt=0)

        // ---- load K/V tile (tf32-rounded), keys >= 341 zero-filled
        const int jbase = kt * 64;
        for (int idx = tid; idx < 64 * 16; idx += FA_THREADS) {
            const int jl = idx >> 4;
            const int d4 = (idx & 15) << 2;
            const int jg = jbase + jl;
            float4 kv = make_float4(0.f, 0.f, 0.f, 0.f);
            float4 vv = make_float4(0.f, 0.f, 0.f, 0.f);
            if (jg < NTOK) {
                const float* rp = base + (size_t)jg * (3 * DMODEL);
                kv = *(const float4*)(rp + DMODEL     + d4);
                vv = *(const float4*)(rp + 2 * DMODEL + d4);
            }
            *(float4*)&Ks[jl * KS_STRIDE + d4] =
                make_float4(to_tf32f(kv.x), to_tf32f(kv.y), to_tf32f(kv.z), to_tf32f(kv.w));
            *(float4*)&Vs[jl * VS_STRIDE + d4] =
                make_float4(to_tf32f(vv.x), to_tf32f(vv.y), to_tf32f(vv.z), to_tf32f(vv.w));
        }
        __syncthreads();

        if (jbase >= wmax) continue;   // whole warp masked for this key tile

        // ---- S = Q @ K^T  (warp tile 32 x 64)
        float s[2][8][4];
        #pragma unroll
        for (int mt = 0; mt < 2; mt++)
            #pragma unroll
            for (int nt = 0; nt < 8; nt++)
                #pragma unroll
                for (int i = 0; i < 4; i++) s[mt][nt][i] = 0.f;

        #pragma unroll
        for (int kk = 0; kk < 8; kk++) {
            uint32_t kb[8][2];
            #pragma unroll
            for (int nt = 0; nt < 8; nt++) {
                kb[nt][0] = __float_as_uint(Ks[(nt * 8 + g) * KS_STRIDE + kk * 8 + ctg    ]);
                kb[nt][1] = __float_as_uint(Ks[(nt * 8 + g) * KS_STRIDE + kk * 8 + ctg + 4]);
            }
            #pragma unroll
            for (int mt = 0; mt < 2; mt++) {
                const int r = (w * 32 + mt * 16 + g) * QS_STRIDE;
                uint32_t a0 = __float_as_uint(Qs[r                 + kk * 8 + ctg    ]);
                uint32_t a1 = __float_as_uint(Qs[r + 8 * QS_STRIDE + kk * 8 + ctg    ]);
                uint32_t a2 = __float_as_uint(Qs[r                 + kk * 8 + ctg + 4]);
                uint32_t a3 = __float_as_uint(Qs[r + 8 * QS_STRIDE + kk * 8 + ctg + 4]);
                #pragma unroll
                for (int nt = 0; nt < 8; nt++)
                    mma_tf32(s[mt][nt], a0, a1, a2, a3, kb[nt][0], kb[nt][1]);
            }
        }

        // ---- P = exp(S/8) with mask; write tf32 P to per-warp smem; accumulate l
        #pragma unroll
        for (int mt = 0; mt < 2; mt++) {
            const int jmA = (mt == 0) ? jm0a : jm1a;
            const int jmB = (mt == 0) ? jm0b : jm1b;
            #pragma unroll
            for (int nt = 0; nt < 8; nt++) {
                const int j0 = jbase + nt * 8 + 2 * ctg;
                float e00 = (j0     < jmA) ? __expf(s[mt][nt][0] * 0.125f) : 0.f;
                float e01 = (j0 + 1 < jmA) ? __expf(s[mt][nt][1] * 0.125f) : 0.f;
                float e10 = (j0     < jmB) ? __expf(s[mt][nt][2] * 0.125f) : 0.f;
                float e11 = (j0 + 1 < jmB) ? __expf(s[mt][nt][3] * 0.125f) : 0.f;
                lsum[mt][0] += e00 + e01;
                lsum[mt][1] += e10 + e11;
                *(float2*)&Pw[(mt * 16 + g    ) * PS_STRIDE + nt * 8 + 2 * ctg] =
                    make_float2(to_tf32f(e00), to_tf32f(e01));
                *(float2*)&Pw[(mt * 16 + g + 8) * PS_STRIDE + nt * 8 + 2 * ctg] =
                    make_float2(to_tf32f(e10), to_tf32f(e11));
            }
        }
        __syncwarp();

        // ---- O += P @ V  (k-dim = 64 keys)
        #pragma unroll
        for (int kk = 0; kk < 8; kk++) {
            uint32_t vb[8][2];
            #pragma unroll
            for (int nt = 0; nt < 8; nt++) {
                vb[nt][0] = __float_as_uint(Vs[(kk * 8 + ctg    ) * VS_STRIDE + nt * 8 + g]);
                vb[nt][1] = __float_as_uint(Vs[(kk * 8 + ctg + 4) * VS_STRIDE + nt * 8 + g]);
            }
            #pragma unroll
            for (int mt = 0; mt < 2; mt++) {
                const int r = (mt * 16 + g) * PS_STRIDE;
                uint32_t a0 = __float_as_uint(Pw[r                 + kk * 8 + ctg    ]);
                uint32_t a1 = __float_as_uint(Pw[r + 8 * PS_STRIDE + kk * 8 + ctg    ]);
                uint32_t a2 = __float_as_uint(Pw[r                 + kk * 8 + ctg + 4]);
                uint32_t a3 = __float_as_uint(Pw[r + 8 * PS_STRIDE + kk * 8 + ctg + 4]);
                #pragma unroll
                for (int nt = 0; nt < 8; nt++)
                    mma_tf32(o[mt][nt], a0, a1, a2, a3, vb[nt][0], vb[nt][1]);
            }
        }
        __syncwarp();
    }

    // ---- normalize and write out
    float inv[2][2];
    #pragma unroll
    for (int mt = 0; mt < 2; mt++)
        #pragma unroll
        for (int rr = 0; rr < 2; rr++) {
            float lv = lsum[mt][rr];
            lv += __shfl_xor_sync(0xFFFFFFFFu, lv, 1);
            lv += __shfl_xor_sync(0xFFFFFFFFu, lv, 2);
            inv[mt][rr] = 1.0f / lv;
        }

    #pragma unroll
    for (int mt = 0; mt < 2; mt++) {
        const int r0 = w * 32 + mt * 16 + g;
        const int r1 = r0 + 8;
        #pragma unroll
        for (int nt = 0; nt < 8; nt++) {
            const int c0 = nt * 8 + 2 * ctg;
            if (r0 < NTOK) {
                float2 v = make_float2(o[mt][nt][0] * inv[mt][0],
                                       o[mt][nt][1] * inv[mt][0]);
                *(float2*)(attn_out + ((size_t)b * NTOK + r0) * DMODEL + h * HDIM + c0) = v;
            }
            if (r1 < NTOK) {
                float2 v = make_float2(o[mt][nt][2] * inv[mt][1],
                                       o[mt][nt][3] * inv[mt][1]);
                *(float2*)(attn_out + ((size_t)b * NTOK + r1) * DMODEL + h * HDIM + c0) = v;
            }
        }
    }
}

// ---------------------------------------------------------------------------
// Launch
// ---------------------------------------------------------------------------
extern "C" void kernel_launch(void* const* d_in, const int* in_sizes, int n_in,
                              void* d_out, int out_size)
{
    const float* x      = (const float*)d_in[0];
    const float* qkv_w  = (const float*)d_in[1];
    const float* qkv_b  = (const float*)d_in[2];
    const float* proj_w = (const float*)d_in[3];
    const float* proj_b = (const float*)d_in[4];
    float* out = (float*)d_out;

    const int Bsz = in_sizes[0] / (NTOK * DMODEL);   // 64
    const int M   = Bsz * NTOK;                      // 21824

    float *qkv_s, *attn_s;
    cudaGetSymbolAddress((void**)&qkv_s,  g_qkv);
    cudaGetSymbolAddress((void**)&attn_s, g_attn);

    // Unconditional (no static guards per harness contract); capture-safe.
    cudaFuncSetAttribute(flash_attn_tf32,
                         cudaFuncAttributeMaxDynamicSharedMemorySize, FA_SMEM_BYTES);

    // 1) QKV GEMM: [M,768] x [2304,768]^T -> [M,2304]
    {
        dim3 grid(3 * DMODEL / 128, (M + 127) / 128);
        gemm_tf32_bias<<<grid, 256>>>(x, qkv_w, qkv_b, qkv_s, M, 3 * DMODEL, DMODEL);
    }
    // 2) Flash attention
    {
        dim3 grid(NHEAD, Bsz);
        flash_attn_tf32<<<grid, FA_THREADS, FA_SMEM_BYTES>>>(qkv_s, attn_s);
    }
    // 3) Proj GEMM: [M,768] x [768,768]^T -> [M,768]
    {
        dim3 grid(DMODEL / 128, (M + 127) / 128);
        gemm_tf32_bias<<<grid, 256>>>(attn_s, proj_w, proj_b, out, M, DMODEL, DMODEL);
    }
}

// round 4
// speedup vs baseline: 1.5649x; 1.0816x over previous
#include <cuda_runtime.h>
#include <cuda_bf16.h>
#include <cstdint>
#include <cstddef>

// ---------------------------------------------------------------------------
// ScaleCausalAttention  (B=64, N=341, D=768, H=12, hd=64, fp32)
//   qkv  = x @ qkv_w^T + qkv_b
//   attn = softmax(q k^T * 0.125 + scale-causal mask) v      (per b,h)
//   out  = attn @ proj_w^T + proj_b
//
// GEMMs: tf32 mma.sync (m16n8k8), 128x128x32 tiles, cp.async double-buffer.
// Attention: tf32 tensor-core flash attention, 1 CTA per (b,h).
// ---------------------------------------------------------------------------

#define NTOK   341
#define DMODEL 768
#define NHEAD  12
#define HDIM   64

// Scratch (allocation-free rule: __device__ globals)
__device__ float g_qkv [64ULL * NTOK * 3 * DMODEL];   // [B*N, 2304]
__device__ float g_attn[64ULL * NTOK * DMODEL];       // [B*N, 768]

// ---------------------------------------------------------------------------
// tf32 helpers
// ---------------------------------------------------------------------------
__device__ __forceinline__ float to_tf32f(float x) {
    uint32_t u;
    asm("cvt.rna.tf32.f32 %0, %1;" : "=r"(u) : "f"(x));
    return __uint_as_float(u);
}
__device__ __forceinline__ uint32_t f2tf32(float x) {
    uint32_t u;
    asm("cvt.rna.tf32.f32 %0, %1;" : "=r"(u) : "f"(x));
    return u;
}

__device__ __forceinline__ void mma_tf32(float c[4],
                                         uint32_t a0, uint32_t a1, uint32_t a2, uint32_t a3,
                                         uint32_t b0, uint32_t b1) {
    asm volatile(
        "mma.sync.aligned.m16n8k8.row.col.f32.tf32.tf32.f32 "
        "{%0,%1,%2,%3}, {%4,%5,%6,%7}, {%8,%9}, {%0,%1,%2,%3};\n"
        : "+f"(c[0]), "+f"(c[1]), "+f"(c[2]), "+f"(c[3])
        : "r"(a0), "r"(a1), "r"(a2), "r"(a3), "r"(b0), "r"(b1));
}

__device__ __forceinline__ void cp_async16(uint32_t saddr, const void* gaddr, int szfill) {
    asm volatile("cp.async.cg.shared.global [%0], [%1], 16, %2;\n"
                 :: "r"(saddr), "l"(gaddr), "r"(szfill));
}
__device__ __forceinline__ void cp_commit() {
    asm volatile("cp.async.commit_group;\n");
}
template <int Nwait>
__device__ __forceinline__ void cp_wait() {
    asm volatile("cp.async.wait_group %0;\n" :: "n"(Nwait));
}

// ---------------------------------------------------------------------------
// GEMM: C[M,N] = A[M,K] @ W[N,K]^T + bias[N]
// Block tile 128x128, K-tile 32, 256 threads, cp.async 2-stage pipeline.
// Raw fp32 staged; tf32 rounding applied at fragment load (same numerics).
// smem per stage: As 128x36 + Bs 128x36 floats; 2 stages = 73728 B dynamic.
// ---------------------------------------------------------------------------
#define GS_TILE   (128 * 36)              // floats per tile buffer
#define GEMM_SMEM (4 * GS_TILE * 4)       // 2 stages x (A+B) = 73728 B

__global__ __launch_bounds__(256, 2)
void gemm_tf32_pipe(const float* __restrict__ A, const float* __restrict__ W,
                    const float* __restrict__ bias, float* __restrict__ C,
                    int M, int N, int K)
{
    extern __shared__ float smg[];
    // layout: [buf0 A][buf1 A][buf0 B][buf1 B]
    const int tid  = threadIdx.x;
    const int bm   = blockIdx.y * 128;
    const int bn   = blockIdx.x * 128;
    const int warp = tid >> 5;
    const int lane = tid & 31;
    const int wm   = (warp >> 2) * 64;
    const int wn   = (warp & 3) * 32;
    const int g    = lane >> 2;
    const int ctg  = lane & 3;

    const int lr = tid >> 3;         // 0..31
    const int lc = (tid & 7) * 4;    // 16B column
    const int T  = K >> 5;           // k-tiles

    float acc[4][4][4];
    #pragma unroll
    for (int mt = 0; mt < 4; mt++)
        #pragma unroll
        for (int nt = 0; nt < 4; nt++)
            #pragma unroll
            for (int i = 0; i < 4; i++) acc[mt][nt][i] = 0.0f;

    // ---- stage one k-tile into buffer `buf`
    auto stage = [&](int kt, int buf) {
        const int k0 = kt * 32;
        float* As = smg + buf * GS_TILE;
        float* Bs = smg + 2 * GS_TILE + buf * GS_TILE;
        #pragma unroll
        for (int i = 0; i < 4; i++) {
            const int row = lr + i * 32;
            const int gm  = bm + row;
            uint32_t sA = (uint32_t)__cvta_generic_to_shared(&As[row * 36 + lc]);
            cp_async16(sA, A + (size_t)gm * K + k0 + lc, (gm < M) ? 16 : 0);
            uint32_t sB = (uint32_t)__cvta_generic_to_shared(&Bs[row * 36 + lc]);
            cp_async16(sB, W + (size_t)(bn + row) * K + k0 + lc, 16);
        }
        cp_commit();
    };

    stage(0, 0);

    for (int kt = 0; kt < T; kt++) {
        const int cur = kt & 1;
        if (kt + 1 < T) { stage(kt + 1, (kt + 1) & 1); cp_wait<1>(); }
        else            { cp_wait<0>(); }
        __syncthreads();

        const float* As = smg + cur * GS_TILE;
        const float* Bs = smg + 2 * GS_TILE + cur * GS_TILE;

        #pragma unroll
        for (int kk = 0; kk < 32; kk += 8) {
            uint32_t af[4][4], bf[4][2];
            #pragma unroll
            for (int mt = 0; mt < 4; mt++) {
                const int r = wm + mt * 16 + g;
                af[mt][0] = f2tf32(As[ r      * 36 + kk + ctg    ]);
                af[mt][1] = f2tf32(As[(r + 8) * 36 + kk + ctg    ]);
                af[mt][2] = f2tf32(As[ r      * 36 + kk + ctg + 4]);
                af[mt][3] = f2tf32(As[(r + 8) * 36 + kk + ctg + 4]);
            }
            #pragma unroll
            for (int nt = 0; nt < 4; nt++) {
                const int c = wn + nt * 8 + g;
                bf[nt][0] = f2tf32(Bs[c * 36 + kk + ctg    ]);
                bf[nt][1] = f2tf32(Bs[c * 36 + kk + ctg + 4]);
            }
            #pragma unroll
            for (int mt = 0; mt < 4; mt++)
                #pragma unroll
                for (int nt = 0; nt < 4; nt++)
                    mma_tf32(acc[mt][nt],
                             af[mt][0], af[mt][1], af[mt][2], af[mt][3],
                             bf[nt][0], bf[nt][1]);
        }
        __syncthreads();   // all reads of `cur` done before it is re-staged
    }

    #pragma unroll
    for (int mt = 0; mt < 4; mt++) {
        #pragma unroll
        for (int nt = 0; nt < 4; nt++) {
            const int r0 = bm + wm + mt * 16 + g;
            const int c0 = bn + wn + nt * 8 + 2 * ctg;
            const float b0 = bias[c0];
            const float b1 = bias[c0 + 1];
            if (r0 < M) {
                float2 v = make_float2(acc[mt][nt][0] + b0, acc[mt][nt][1] + b1);
                *(float2*)(C + (size_t)r0 * N + c0) = v;
            }
            if (r0 + 8 < M) {
                float2 v = make_float2(acc[mt][nt][2] + b0, acc[mt][nt][3] + b1);
                *(float2*)(C + (size_t)(r0 + 8) * N + c0) = v;
            }
        }
    }
}

// ---------------------------------------------------------------------------
// Flash attention (tf32 tensor cores), one CTA per (b,h).  (unchanged)
// ---------------------------------------------------------------------------
#define FA_THREADS 352
#define QS_STRIDE  68
#define KS_STRIDE  68
#define VS_STRIDE  72
#define PS_STRIDE  68
#define QS_FLOATS  (352 * QS_STRIDE)
#define KS_FLOATS  (64 * KS_STRIDE)
#define VS_FLOATS  (64 * VS_STRIDE)
#define PS_FLOATS  (11 * 32 * PS_STRIDE)
#define FA_SMEM_FLOATS (QS_FLOATS + KS_FLOATS + VS_FLOATS + PS_FLOATS)
#define FA_SMEM_BYTES  (FA_SMEM_FLOATS * 4)   // 227328 B

__device__ __forceinline__ int jmax_of(int t) {
    if (t >= 341) return 5;
    if (t == 0 || t >= 85) return 341;
    if (t < 5)  return 5;
    if (t < 21) return 21;
    return 85;
}

__global__ __launch_bounds__(FA_THREADS, 1)
void flash_attn_tf32(const float* __restrict__ qkv, float* __restrict__ attn_out)
{
    extern __shared__ float sm[];
    float* Qs = sm;
    float* Ks = Qs + QS_FLOATS;
    float* Vs = Ks + KS_FLOATS;
    float* Pb = Vs + VS_FLOATS;

    const int h   = blockIdx.x;
    const int b   = blockIdx.y;
    const int tid = threadIdx.x;
    const int w   = tid >> 5;
    const int lane = tid & 31;
    const int g    = lane >> 2;
    const int ctg  = lane & 3;
    float* Pw = Pb + w * 32 * PS_STRIDE;

    const float* base = qkv + (size_t)b * NTOK * (3 * DMODEL) + h * HDIM;

    for (int idx = tid; idx < 352 * 16; idx += FA_THREADS) {
        const int row = idx >> 4;
        const int d4  = (idx & 15) << 2;
        float4 v = make_float4(0.f, 0.f, 0.f, 0.f);
        if (row < NTOK) v = *(const float4*)(base + (size_t)row * (3 * DMODEL) + d4);
        *(float4*)&Qs[row * QS_STRIDE + d4] =
            make_float4(to_tf32f(v.x), to_tf32f(v.y), to_tf32f(v.z), to_tf32f(v.w));
    }

    float o[2][8][4];
    #pragma unroll
    for (int mt = 0; mt < 2; mt++)
        #pragma unroll
        for (int nt = 0; nt < 8; nt++)
            #pragma unroll
            for (int i = 0; i < 4; i++) o[mt][nt][i] = 0.f;
    float lsum[2][2] = {{0.f, 0.f}, {0.f, 0.f}};

    const int wmax = (w == 1) ? 85 : 341;
    const int jm0a = jmax_of(w * 32      + g);
    const int jm0b = jmax_of(w * 32 +  8 + g);
    const int jm1a = jmax_of(w * 32 + 16 + g);
    const int jm1b = jmax_of(w * 32 + 24 + g);

    for (int kt = 0; kt < 6; kt++) {
        __syncthreads();

        const int jbase = kt * 64;
        for (int idx = tid; idx < 64 * 16; idx += FA_THREADS) {
            const int jl = idx >> 4;
            const int d4 = (idx & 15) << 2;
            const int jg = jbase + jl;
            float4 kv = make_float4(0.f, 0.f, 0.f, 0.f);
            float4 vv = make_float4(0.f, 0.f, 0.f, 0.f);
            if (jg < NTOK) {
                const float* rp = base + (size_t)jg * (3 * DMODEL);
                kv = *(const float4*)(rp + DMODEL     + d4);
                vv = *(const float4*)(rp + 2 * DMODEL + d4);
            }
            *(float4*)&Ks[jl * KS_STRIDE + d4] =
                make_float4(to_tf32f(kv.x), to_tf32f(kv.y), to_tf32f(kv.z), to_tf32f(kv.w));
            *(float4*)&Vs[jl * VS_STRIDE + d4] =
                make_float4(to_tf32f(vv.x), to_tf32f(vv.y), to_tf32f(vv.z), to_tf32f(vv.w));
        }
        __syncthreads();

        if (jbase >= wmax) continue;

        float s[2][8][4];
        #pragma unroll
        for (int mt = 0; mt < 2; mt++)
            #pragma unroll
            for (int nt = 0; nt < 8; nt++)
                #pragma unroll
                for (int i = 0; i < 4; i++) s[mt][nt][i] = 0.f;

        #pragma unroll
        for (int kk = 0; kk < 8; kk++) {
            uint32_t kb[8][2];
            #pragma unroll
            for (int nt = 0; nt < 8; nt++) {
                kb[nt][0] = __float_as_uint(Ks[(nt * 8 + g) * KS_STRIDE + kk * 8 + ctg    ]);
                kb[nt][1] = __float_as_uint(Ks[(nt * 8 + g) * KS_STRIDE + kk * 8 + ctg + 4]);
            }
            #pragma unroll
            for (int mt = 0; mt < 2; mt++) {
                const int r = (w * 32 + mt * 16 + g) * QS_STRIDE;
                uint32_t a0 = __float_as_uint(Qs[r                 + kk * 8 + ctg    ]);
                uint32_t a1 = __float_as_uint(Qs[r + 8 * QS_STRIDE + kk * 8 + ctg    ]);
                uint32_t a2 = __float_as_uint(Qs[r                 + kk * 8 + ctg + 4]);
                uint32_t a3 = __float_as_uint(Qs[r + 8 * QS_STRIDE + kk * 8 + ctg + 4]);
                #pragma unroll
                for (int nt = 0; nt < 8; nt++)
                    mma_tf32(s[mt][nt], a0, a1, a2, a3, kb[nt][0], kb[nt][1]);
            }
        }

        #pragma unroll
        for (int mt = 0; mt < 2; mt++) {
            const int jmA = (mt == 0) ? jm0a : jm1a;
            const int jmB = (mt == 0) ? jm0b : jm1b;
            #pragma unroll
            for (int nt = 0; nt < 8; nt++) {
                const int j0 = jbase + nt * 8 + 2 * ctg;
                float e00 = (j0     < jmA) ? __expf(s[mt][nt][0] * 0.125f) : 0.f;
                float e01 = (j0 + 1 < jmA) ? __expf(s[mt][nt][1] * 0.125f) : 0.f;
                float e10 = (j0     < jmB) ? __expf(s[mt][nt][2] * 0.125f) : 0.f;
                float e11 = (j0 + 1 < jmB) ? __expf(s[mt][nt][3] * 0.125f) : 0.f;
                lsum[mt][0] += e00 + e01;
                lsum[mt][1] += e10 + e11;
                *(float2*)&Pw[(mt * 16 + g    ) * PS_STRIDE + nt * 8 + 2 * ctg] =
                    make_float2(to_tf32f(e00), to_tf32f(e01));
                *(float2*)&Pw[(mt * 16 + g + 8) * PS_STRIDE + nt * 8 + 2 * ctg] =
                    make_float2(to_tf32f(e10), to_tf32f(e11));
            }
        }
        __syncwarp();

        #pragma unroll
        for (int kk = 0; kk < 8; kk++) {
            uint32_t vb[8][2];
            #pragma unroll
            for (int nt = 0; nt < 8; nt++) {
                vb[nt][0] = __float_as_uint(Vs[(kk * 8 + ctg    ) * VS_STRIDE + nt * 8 + g]);
                vb[nt][1] = __float_as_uint(Vs[(kk * 8 + ctg + 4) * VS_STRIDE + nt * 8 + g]);
            }
            #pragma unroll
            for (int mt = 0; mt < 2; mt++) {
                const int r = (mt * 16 + g) * PS_STRIDE;
                uint32_t a0 = __float_as_uint(Pw[r                 + kk * 8 + ctg    ]);
                uint32_t a1 = __float_as_uint(Pw[r + 8 * PS_STRIDE + kk * 8 + ctg    ]);
                uint32_t a2 = __float_as_uint(Pw[r                 + kk * 8 + ctg + 4]);
                uint32_t a3 = __float_as_uint(Pw[r + 8 * PS_STRIDE + kk * 8 + ctg + 4]);
                #pragma unroll
                for (int nt = 0; nt < 8; nt++)
                    mma_tf32(o[mt][nt], a0, a1, a2, a3, vb[nt][0], vb[nt][1]);
            }
        }
        __syncwarp();
    }

    float inv[2][2];
    #pragma unroll
    for (int mt = 0; mt < 2; mt++)
        #pragma unroll
        for (int rr = 0; rr < 2; rr++) {
            float lv = lsum[mt][rr];
            lv += __shfl_xor_sync(0xFFFFFFFFu, lv, 1);
            lv += __shfl_xor_sync(0xFFFFFFFFu, lv, 2);
            inv[mt][rr] = 1.0f / lv;
        }

    #pragma unroll
    for (int mt = 0; mt < 2; mt++) {
        const int r0 = w * 32 + mt * 16 + g;
        const int r1 = r0 + 8;
        #pragma unroll
        for (int nt = 0; nt < 8; nt++) {
            const int c0 = nt * 8 + 2 * ctg;
            if (r0 < NTOK) {
                float2 v = make_float2(o[mt][nt][0] * inv[mt][0],
                                       o[mt][nt][1] * inv[mt][0]);
                *(float2*)(attn_out + ((size_t)b * NTOK + r0) * DMODEL + h * HDIM + c0) = v;
            }
            if (r1 < NTOK) {
                float2 v = make_float2(o[mt][nt][2] * inv[mt][1],
                                       o[mt][nt][3] * inv[mt][1]);
                *(float2*)(attn_out + ((size_t)b * NTOK + r1) * DMODEL + h * HDIM + c0) = v;
            }
        }
    }
}

// ---------------------------------------------------------------------------
// Launch
// ---------------------------------------------------------------------------
extern "C" void kernel_launch(void* const* d_in, const int* in_sizes, int n_in,
                              void* d_out, int out_size)
{
    const float* x      = (const float*)d_in[0];
    const float* qkv_w  = (const float*)d_in[1];
    const float* qkv_b  = (const float*)d_in[2];
    const float* proj_w = (const float*)d_in[3];
    const float* proj_b = (const float*)d_in[4];
    float* out = (float*)d_out;

    const int Bsz = in_sizes[0] / (NTOK * DMODEL);   // 64
    const int M   = Bsz * NTOK;                      // 21824

    float *qkv_s, *attn_s;
    cudaGetSymbolAddress((void**)&qkv_s,  g_qkv);
    cudaGetSymbolAddress((void**)&attn_s, g_attn);

    cudaFuncSetAttribute(gemm_tf32_pipe,
                         cudaFuncAttributeMaxDynamicSharedMemorySize, GEMM_SMEM);
    cudaFuncSetAttribute(flash_attn_tf32,
                         cudaFuncAttributeMaxDynamicSharedMemorySize, FA_SMEM_BYTES);

    // 1) QKV GEMM: [M,768] x [2304,768]^T -> [M,2304]
    {
        dim3 grid(3 * DMODEL / 128, (M + 127) / 128);
        gemm_tf32_pipe<<<grid, 256, GEMM_SMEM>>>(x, qkv_w, qkv_b, qkv_s, M, 3 * DMODEL, DMODEL);
    }
    // 2) Flash attention
    {
        dim3 grid(NHEAD, Bsz);
        flash_attn_tf32<<<grid, FA_THREADS, FA_SMEM_BYTES>>>(qkv_s, attn_s);
    }
    // 3) Proj GEMM: [M,768] x [768,768]^T -> [M,768]
    {
        dim3 grid(DMODEL / 128, (M + 127) / 128);
        gemm_tf32_pipe<<<grid, 256, GEMM_SMEM>>>(attn_s, proj_w, proj_b, out, M, DMODEL, DMODEL);
    }
}